// round 6
// baseline (speedup 1.0000x reference)
#include <cuda_runtime.h>
#include <math.h>

// Problem constants
constexpr int cN   = 4;
constexpr int cH   = 128;
constexpr int cW   = 256;
constexpr int CIN1 = 96,  COUT1 = 128;
constexpr int CIN2 = 128, COUT2 = 144;
constexpr int HW   = cH * cW;

// Scratch (static device allocation — no cudaMalloc allowed)
__device__ float g_hfeat[cN * COUT1 * cH * cW];
__device__ float g_mask [cN * COUT2 * cH * cW];

// ---- packed f32x2 helpers ----------------------------------------------
using ull = unsigned long long;

__device__ __forceinline__ ull pk_dup(float x) {
    ull r;
    asm("mov.b64 %0, {%1, %1};" : "=l"(r) : "f"(x));
    return r;
}
__device__ __forceinline__ void fma2(ull& d, ull a, ull b) {
    asm("fma.rn.f32x2 %0, %1, %2, %0;" : "+l"(d) : "l"(a), "l"(b));
}
__device__ __forceinline__ void unpk(float& lo, float& hi, ull v) {
    asm("mov.b64 {%0, %1}, %2;" : "=f"(lo), "=f"(hi) : "l"(v));
}

// ---------------------------------------------------------------------------
// 3x3 SAME conv, NCHW, register-blocked implicit GEMM with packed f32x2 FMA.
// Tile: NT=128 pixels (half a row) x MT output channels.
// 256 threads = 32 (pixel groups, 4 px each) x 8 (channel groups, MR ch each).
// f32x2 packs over the CHANNEL dim: weight pairs come straight out of smem
// as 8-byte LDS.64 broadcasts; only the pixel broadcast needs a dup MOV.
// WPAD chosen so the weight-staging STS stride is 6 banks (2-way conflict
// max) while keeping rows 8B-aligned for the compute-side LDS.64.
// ---------------------------------------------------------------------------
template<int CIN, int COUT, int MT, bool LRELU>
__global__ __launch_bounds__(256, 3)
void conv3x3_kernel(const float* __restrict__ in,
                    const float* __restrict__ wt,
                    const float* __restrict__ bias,
                    float* __restrict__ out)
{
    constexpr int NT    = 128;
    constexpr int KC    = 8;
    constexpr int KSTEP = KC * 9;          // 72
    constexpr int MR    = MT / 8;          // 8 (MT=64) or 6 (MT=48)
    constexpr int MP    = MR / 2;          // channel pairs per thread
    constexpr int IPAD  = NT + 4;          // 132: 16B-aligned rows
    constexpr int WPAD  = MT + 6;          // 70 / 54: stride%32 = 6 -> 2-way

    __shared__ __align__(16) float s_in[KC][3][IPAD];
    __shared__ __align__(16) float s_w[KSTEP][WPAD];

    const int tid = threadIdx.x;
    const int tx  = tid & 31;    // pixel group: pixels tx*4 .. tx*4+3
    const int ty  = tid >> 5;    // channel group: channels ty*MR .. +MR-1

    const int x0 = blockIdx.x * NT;
    const int y  = blockIdx.y;
    constexpr int MTILES = COUT / MT;
    const int n   = blockIdx.z / MTILES;
    const int co0 = (blockIdx.z % MTILES) * MT;

    ull acc[MP][4];
    #pragma unroll
    for (int p = 0; p < MP; p++)
        #pragma unroll
        for (int j = 0; j < 4; j++) acc[p][j] = 0ull;

    for (int ci0 = 0; ci0 < CIN; ci0 += KC) {
        __syncthreads();  // protect previous chunk's smem reads

        // --- stage input tile: KC channels x 3 rows x (NT+2) cols (halo) ---
        constexpr int IN_ELEMS = KC * 3 * (NT + 2);
        #pragma unroll 4
        for (int idx = tid; idx < IN_ELEMS; idx += 256) {
            int ci  = idx / (3 * (NT + 2));
            int rem = idx % (3 * (NT + 2));
            int ky  = rem / (NT + 2);
            int xx  = rem % (NT + 2);
            int gy = y + ky - 1;
            int gx = x0 + xx - 1;
            float v = 0.0f;
            if ((unsigned)gy < (unsigned)cH && (unsigned)gx < (unsigned)cW)
                v = in[((n * CIN + ci0 + ci) * cH + gy) * cW + gx];
            s_in[ci][ky][xx] = v;
        }

        // --- stage weights k-major: s_w[k][co_l] (coalesced global reads) ---
        constexpr int W_ELEMS = MT * KSTEP;
        #pragma unroll 4
        for (int idx = tid; idx < W_ELEMS; idx += 256) {
            int co_l = idx / KSTEP;
            int kk   = idx % KSTEP;
            s_w[kk][co_l] = wt[((co0 + co_l) * CIN + ci0) * 9 + kk];
        }
        __syncthreads();

        // --- compute: 72 k-steps; 6-wide sliding pixel window per (ci,ky) ---
        #pragma unroll
        for (int ci = 0; ci < KC; ci++) {
            #pragma unroll
            for (int ky = 0; ky < 3; ky++) {
                const float* bp = &s_in[ci][ky][tx * 4];
                float4 blo = *reinterpret_cast<const float4*>(bp);
                float2 bhi = *reinterpret_cast<const float2*>(bp + 4);
                ull bd[6];
                bd[0] = pk_dup(blo.x); bd[1] = pk_dup(blo.y);
                bd[2] = pk_dup(blo.z); bd[3] = pk_dup(blo.w);
                bd[4] = pk_dup(bhi.x); bd[5] = pk_dup(bhi.y);
                #pragma unroll
                for (int kx = 0; kx < 3; kx++) {
                    const int k = ci * 9 + ky * 3 + kx;
                    const ull* ap = reinterpret_cast<const ull*>(&s_w[k][ty * MR]);
                    #pragma unroll
                    for (int p = 0; p < MP; p++) {
                        const ull a = ap[p];   // weight pair (co, co+1)
                        #pragma unroll
                        for (int j = 0; j < 4; j++)
                            fma2(acc[p][j], a, bd[kx + j]);
                    }
                }
            }
        }
    }

    // --- epilogue: unpack channel pairs, bias (+ LeakyReLU), vector store ---
    #pragma unroll
    for (int p = 0; p < MP; p++) {
        float lo[4], hi[4];
        #pragma unroll
        for (int j = 0; j < 4; j++) unpk(lo[j], hi[j], acc[p][j]);

        #pragma unroll
        for (int half = 0; half < 2; half++) {
            const int co = co0 + ty * MR + 2 * p + half;
            const float bs = __ldg(&bias[co]);
            const float* v4 = half ? hi : lo;
            float4 v;
            v.x = v4[0] + bs; v.y = v4[1] + bs;
            v.z = v4[2] + bs; v.w = v4[3] + bs;
            if (LRELU) {
                v.x = v.x > 0.f ? v.x : 0.1f * v.x;
                v.y = v.y > 0.f ? v.y : 0.1f * v.y;
                v.z = v.z > 0.f ? v.z : 0.1f * v.z;
                v.w = v.w > 0.f ? v.w : 0.1f * v.w;
            }
            *reinterpret_cast<float4*>(
                &out[((n * COUT + co) * cH + y) * cW + x0 + tx * 4]) = v;
        }
    }
}

// ---------------------------------------------------------------------------
// Softmax over 9 kernel positions + convex combination + 4x pixel shuffle.
// One thread per (n, y, x). mask channel layout: k*16 + a*4 + b.
// ---------------------------------------------------------------------------
__global__ __launch_bounds__(256)
void upsample_kernel(const float* __restrict__ flow,
                     const float* __restrict__ mask,
                     float* __restrict__ out)
{
    const int idx = blockIdx.x * blockDim.x + threadIdx.x;
    if (idx >= cN * HW) return;
    const int x = idx % cW;
    const int y = (idx / cW) % cH;
    const int n = idx / HW;

    float fpx[9], fpy[9];
    #pragma unroll
    for (int ki = 0; ki < 3; ki++)
        #pragma unroll
        for (int kj = 0; kj < 3; kj++) {
            const int k = ki * 3 + kj;
            const int yy = y + ki - 1, xx = x + kj - 1;
            const bool ok = (unsigned)yy < (unsigned)cH && (unsigned)xx < (unsigned)cW;
            fpx[k] = ok ? 4.0f * flow[(n * 2 + 0) * HW + yy * cW + xx] : 0.0f;
            fpy[k] = ok ? 4.0f * flow[(n * 2 + 1) * HW + yy * cW + xx] : 0.0f;
        }

    const long base = (long)n * COUT2 * HW + y * cW + x;
    const int OH = 4 * cH, OW = 4 * cW;

    #pragma unroll
    for (int a = 0; a < 4; a++) {
        #pragma unroll
        for (int b = 0; b < 4; b++) {
            float m[9];
            float mx = -1e30f;
            #pragma unroll
            for (int k = 0; k < 9; k++) {
                m[k] = 0.25f * mask[base + (long)(k * 16 + a * 4 + b) * HW];
                mx = fmaxf(mx, m[k]);
            }
            float s = 0.0f;
            #pragma unroll
            for (int k = 0; k < 9; k++) { m[k] = __expf(m[k] - mx); s += m[k]; }
            const float inv = 1.0f / s;
            float ox = 0.0f, oy = 0.0f;
            #pragma unroll
            for (int k = 0; k < 9; k++) { ox += m[k] * fpx[k]; oy += m[k] * fpy[k]; }
            const int oyi = y * 4 + a, oxi = x * 4 + b;
            out[((n * 2 + 0) * OH + oyi) * OW + oxi] = ox * inv;
            out[((n * 2 + 1) * OH + oyi) * OW + oxi] = oy * inv;
        }
    }
}

// ---------------------------------------------------------------------------
extern "C" void kernel_launch(void* const* d_in, const int* in_sizes, int n_in,
                              void* d_out, int out_size)
{
    (void)in_sizes; (void)n_in; (void)out_size;
    const float* flow = (const float*)d_in[0];
    const float* feat = (const float*)d_in[1];
    const float* w1   = (const float*)d_in[2];
    const float* b1   = (const float*)d_in[3];
    const float* w2   = (const float*)d_in[4];
    const float* b2   = (const float*)d_in[5];
    float* out = (float*)d_out;

    float* hfeat; float* msk;
    cudaGetSymbolAddress((void**)&hfeat, g_hfeat);
    cudaGetSymbolAddress((void**)&msk, g_mask);

    // conv1: 96 -> 128, LeakyReLU(0.1). MT=64 -> 2 exact channel tiles, MR=8.
    {
        dim3 grid(cW / 128, cH, cN * (COUT1 / 64));
        conv3x3_kernel<CIN1, COUT1, 64, true><<<grid, 256>>>(feat, w1, b1, hfeat);
    }
    // conv2: 128 -> 144 (raw; 0.25 folded into softmax). MT=48 -> 3 tiles, MR=6.
    {
        dim3 grid(cW / 128, cH, cN * (COUT2 / 48));
        conv3x3_kernel<CIN2, COUT2, 48, false><<<grid, 256>>>(hfeat, w2, b2, msk);
    }
    // softmax + convex upsample + pixel shuffle
    {
        const int total = cN * HW;
        upsample_kernel<<<(total + 255) / 256, 256>>>(flow, msk, out);
    }
}

// round 7
// speedup vs baseline: 1.0007x; 1.0007x over previous
#include <cuda_runtime.h>
#include <math.h>

// Problem constants
constexpr int cN   = 4;
constexpr int cH   = 128;
constexpr int cW   = 256;
constexpr int CIN1 = 96,  COUT1 = 128;
constexpr int CIN2 = 128, COUT2 = 144;
constexpr int HW   = cH * cW;

// Scratch (static device allocation — no cudaMalloc allowed)
__device__ float g_hfeat[cN * COUT1 * cH * cW];
__device__ float g_mask [cN * COUT2 * cH * cW];

// ---- packed f32x2 helpers ----------------------------------------------
using ull = unsigned long long;

__device__ __forceinline__ ull pk_dup(float x) {
    ull r;
    asm("mov.b64 %0, {%1, %1};" : "=l"(r) : "f"(x));
    return r;
}
__device__ __forceinline__ void fma2(ull& d, ull a, ull b) {
    asm("fma.rn.f32x2 %0, %1, %2, %0;" : "+l"(d) : "l"(a), "l"(b));
}
__device__ __forceinline__ void unpk(float& lo, float& hi, ull v) {
    asm("mov.b64 {%0, %1}, %2;" : "=f"(lo), "=f"(hi) : "l"(v));
}

// ---------------------------------------------------------------------------
// 3x3 SAME conv, NCHW, register-blocked implicit GEMM with packed f32x2 FMA.
// Tile: NT=128 pixels (half a row) x MT output channels.
// 256 threads = 32 (pixel groups, 4 px each) x 8 (channel groups, MR ch each).
// f32x2 packs over the CHANNEL dim: weight pairs come straight out of smem
// as 8-byte LDS.64 broadcasts; only the pixel broadcast needs a dup MOV.
// WPAD chosen so the weight-staging STS stride is 6 banks (2-way conflict
// max) while keeping rows 8B-aligned for the compute-side LDS.64.
// ---------------------------------------------------------------------------
template<int CIN, int COUT, int MT, bool LRELU>
__global__ __launch_bounds__(256, 3)
void conv3x3_kernel(const float* __restrict__ in,
                    const float* __restrict__ wt,
                    const float* __restrict__ bias,
                    float* __restrict__ out)
{
    constexpr int NT    = 128;
    constexpr int KC    = 8;
    constexpr int KSTEP = KC * 9;          // 72
    constexpr int MR    = MT / 8;          // 8 (MT=64) or 6 (MT=48)
    constexpr int MP    = MR / 2;          // channel pairs per thread
    constexpr int IPAD  = NT + 4;          // 132: 16B-aligned rows
    constexpr int WPAD  = MT + 6;          // 70 / 54: stride%32 = 6 -> 2-way

    __shared__ __align__(16) float s_in[KC][3][IPAD];
    __shared__ __align__(16) float s_w[KSTEP][WPAD];

    const int tid = threadIdx.x;
    const int tx  = tid & 31;    // pixel group: pixels tx*4 .. tx*4+3
    const int ty  = tid >> 5;    // channel group: channels ty*MR .. +MR-1

    const int x0 = blockIdx.x * NT;
    const int y  = blockIdx.y;
    constexpr int MTILES = COUT / MT;
    const int n   = blockIdx.z / MTILES;
    const int co0 = (blockIdx.z % MTILES) * MT;

    ull acc[MP][4];
    #pragma unroll
    for (int p = 0; p < MP; p++)
        #pragma unroll
        for (int j = 0; j < 4; j++) acc[p][j] = 0ull;

    for (int ci0 = 0; ci0 < CIN; ci0 += KC) {
        __syncthreads();  // protect previous chunk's smem reads

        // --- stage input tile: KC channels x 3 rows x (NT+2) cols (halo) ---
        constexpr int IN_ELEMS = KC * 3 * (NT + 2);
        #pragma unroll 4
        for (int idx = tid; idx < IN_ELEMS; idx += 256) {
            int ci  = idx / (3 * (NT + 2));
            int rem = idx % (3 * (NT + 2));
            int ky  = rem / (NT + 2);
            int xx  = rem % (NT + 2);
            int gy = y + ky - 1;
            int gx = x0 + xx - 1;
            float v = 0.0f;
            if ((unsigned)gy < (unsigned)cH && (unsigned)gx < (unsigned)cW)
                v = in[((n * CIN + ci0 + ci) * cH + gy) * cW + gx];
            s_in[ci][ky][xx] = v;
        }

        // --- stage weights k-major: s_w[k][co_l] (coalesced global reads) ---
        constexpr int W_ELEMS = MT * KSTEP;
        #pragma unroll 4
        for (int idx = tid; idx < W_ELEMS; idx += 256) {
            int co_l = idx / KSTEP;
            int kk   = idx % KSTEP;
            s_w[kk][co_l] = wt[((co0 + co_l) * CIN + ci0) * 9 + kk];
        }
        __syncthreads();

        // --- compute: 72 k-steps; 6-wide sliding pixel window per (ci,ky) ---
        #pragma unroll
        for (int ci = 0; ci < KC; ci++) {
            #pragma unroll
            for (int ky = 0; ky < 3; ky++) {
                const float* bp = &s_in[ci][ky][tx * 4];
                float4 blo = *reinterpret_cast<const float4*>(bp);
                float2 bhi = *reinterpret_cast<const float2*>(bp + 4);
                ull bd[6];
                bd[0] = pk_dup(blo.x); bd[1] = pk_dup(blo.y);
                bd[2] = pk_dup(blo.z); bd[3] = pk_dup(blo.w);
                bd[4] = pk_dup(bhi.x); bd[5] = pk_dup(bhi.y);
                #pragma unroll
                for (int kx = 0; kx < 3; kx++) {
                    const int k = ci * 9 + ky * 3 + kx;
                    const ull* ap = reinterpret_cast<const ull*>(&s_w[k][ty * MR]);
                    #pragma unroll
                    for (int p = 0; p < MP; p++) {
                        const ull a = ap[p];   // weight pair (co, co+1)
                        #pragma unroll
                        for (int j = 0; j < 4; j++)
                            fma2(acc[p][j], a, bd[kx + j]);
                    }
                }
            }
        }
    }

    // --- epilogue: unpack channel pairs, bias (+ LeakyReLU), vector store ---
    #pragma unroll
    for (int p = 0; p < MP; p++) {
        float lo[4], hi[4];
        #pragma unroll
        for (int j = 0; j < 4; j++) unpk(lo[j], hi[j], acc[p][j]);

        #pragma unroll
        for (int half = 0; half < 2; half++) {
            const int co = co0 + ty * MR + 2 * p + half;
            const float bs = __ldg(&bias[co]);
            const float* v4 = half ? hi : lo;
            float4 v;
            v.x = v4[0] + bs; v.y = v4[1] + bs;
            v.z = v4[2] + bs; v.w = v4[3] + bs;
            if (LRELU) {
                v.x = v.x > 0.f ? v.x : 0.1f * v.x;
                v.y = v.y > 0.f ? v.y : 0.1f * v.y;
                v.z = v.z > 0.f ? v.z : 0.1f * v.z;
                v.w = v.w > 0.f ? v.w : 0.1f * v.w;
            }
            *reinterpret_cast<float4*>(
                &out[((n * COUT + co) * cH + y) * cW + x0 + tx * 4]) = v;
        }
    }
}

// ---------------------------------------------------------------------------
// Softmax over 9 kernel positions + convex combination + 4x pixel shuffle.
// One thread per (n, y, x). mask channel layout: k*16 + a*4 + b.
// ---------------------------------------------------------------------------
__global__ __launch_bounds__(256)
void upsample_kernel(const float* __restrict__ flow,
                     const float* __restrict__ mask,
                     float* __restrict__ out)
{
    const int idx = blockIdx.x * blockDim.x + threadIdx.x;
    if (idx >= cN * HW) return;
    const int x = idx % cW;
    const int y = (idx / cW) % cH;
    const int n = idx / HW;

    float fpx[9], fpy[9];
    #pragma unroll
    for (int ki = 0; ki < 3; ki++)
        #pragma unroll
        for (int kj = 0; kj < 3; kj++) {
            const int k = ki * 3 + kj;
            const int yy = y + ki - 1, xx = x + kj - 1;
            const bool ok = (unsigned)yy < (unsigned)cH && (unsigned)xx < (unsigned)cW;
            fpx[k] = ok ? 4.0f * flow[(n * 2 + 0) * HW + yy * cW + xx] : 0.0f;
            fpy[k] = ok ? 4.0f * flow[(n * 2 + 1) * HW + yy * cW + xx] : 0.0f;
        }

    const long base = (long)n * COUT2 * HW + y * cW + x;
    const int OH = 4 * cH, OW = 4 * cW;

    #pragma unroll
    for (int a = 0; a < 4; a++) {
        #pragma unroll
        for (int b = 0; b < 4; b++) {
            float m[9];
            float mx = -1e30f;
            #pragma unroll
            for (int k = 0; k < 9; k++) {
                m[k] = 0.25f * mask[base + (long)(k * 16 + a * 4 + b) * HW];
                mx = fmaxf(mx, m[k]);
            }
            float s = 0.0f;
            #pragma unroll
            for (int k = 0; k < 9; k++) { m[k] = __expf(m[k] - mx); s += m[k]; }
            const float inv = 1.0f / s;
            float ox = 0.0f, oy = 0.0f;
            #pragma unroll
            for (int k = 0; k < 9; k++) { ox += m[k] * fpx[k]; oy += m[k] * fpy[k]; }
            const int oyi = y * 4 + a, oxi = x * 4 + b;
            out[((n * 2 + 0) * OH + oyi) * OW + oxi] = ox * inv;
            out[((n * 2 + 1) * OH + oyi) * OW + oxi] = oy * inv;
        }
    }
}

// ---------------------------------------------------------------------------
extern "C" void kernel_launch(void* const* d_in, const int* in_sizes, int n_in,
                              void* d_out, int out_size)
{
    (void)in_sizes; (void)n_in; (void)out_size;
    const float* flow = (const float*)d_in[0];
    const float* feat = (const float*)d_in[1];
    const float* w1   = (const float*)d_in[2];
    const float* b1   = (const float*)d_in[3];
    const float* w2   = (const float*)d_in[4];
    const float* b2   = (const float*)d_in[5];
    float* out = (float*)d_out;

    float* hfeat; float* msk;
    cudaGetSymbolAddress((void**)&hfeat, g_hfeat);
    cudaGetSymbolAddress((void**)&msk, g_mask);

    // conv1: 96 -> 128, LeakyReLU(0.1). MT=64 -> 2 exact channel tiles, MR=8.
    {
        dim3 grid(cW / 128, cH, cN * (COUT1 / 64));
        conv3x3_kernel<CIN1, COUT1, 64, true><<<grid, 256>>>(feat, w1, b1, hfeat);
    }
    // conv2: 128 -> 144 (raw; 0.25 folded into softmax). MT=48 -> 3 tiles, MR=6.
    {
        dim3 grid(cW / 128, cH, cN * (COUT2 / 48));
        conv3x3_kernel<CIN2, COUT2, 48, false><<<grid, 256>>>(hfeat, w2, b2, msk);
    }
    // softmax + convex upsample + pixel shuffle
    {
        const int total = cN * HW;
        upsample_kernel<<<(total + 255) / 256, 256>>>(flow, msk, out);
    }
}

// round 9
// speedup vs baseline: 2.4692x; 2.4676x over previous
#include <cuda_runtime.h>
#include <cuda_bf16.h>
#include <cstdint>
#include <math.h>

constexpr int cN = 4, cH = 128, cW = 256;
constexpr int CIN1 = 96,  COUT1 = 128;
constexpr int CIN2 = 128, COUT2 = 144;
constexpr int HW = cH * cW, Hp = cH + 2, Wp = cW + 2;
constexpr int NPX = cN * Hp * Wp;

// Static scratch (16B-aligned for cp.async / uint4)
__device__ __align__(256) __nv_bfloat16 g_A1h[(size_t)NPX * CIN1];
__device__ __align__(256) __nv_bfloat16 g_A1l[(size_t)NPX * CIN1];
__device__ __align__(256) __nv_bfloat16 g_A2h[(size_t)NPX * CIN2];
__device__ __align__(256) __nv_bfloat16 g_A2l[(size_t)NPX * CIN2];
__device__ __align__(256) __nv_bfloat16 g_W1[9 * 3 * 2 * COUT1 * 32];
__device__ __align__(256) __nv_bfloat16 g_W2[9 * 4 * 2 * COUT2 * 32];
__device__ __align__(256) float g_mask[(size_t)cN * COUT2 * HW];

// ---------------- helpers ----------------------------------------------------
__device__ __forceinline__ uint32_t smem_u32(const void* p) {
    uint32_t a;
    asm("{ .reg .u64 t; cvta.to.shared.u64 t, %1; cvt.u32.u64 %0, t; }" : "=r"(a) : "l"(p));
    return a;
}
__device__ __forceinline__ void cpa16(uint32_t s, const void* g) {
    asm volatile("cp.async.cg.shared.global [%0], [%1], 16;" :: "r"(s), "l"(g) : "memory");
}
__device__ __forceinline__ uint32_t lds32(uint32_t a) {
    uint32_t v;
    asm("ld.shared.b32 %0, [%1];" : "=r"(v) : "r"(a));
    return v;
}
__device__ __forceinline__ void mma_bf16(float* d, const uint32_t* a, uint32_t b0, uint32_t b1) {
    asm volatile("mma.sync.aligned.m16n8k16.row.col.f32.bf16.bf16.f32 "
        "{%0,%1,%2,%3}, {%4,%5,%6,%7}, {%8,%9}, {%0,%1,%2,%3};"
        : "+f"(d[0]), "+f"(d[1]), "+f"(d[2]), "+f"(d[3])
        : "r"(a[0]), "r"(a[1]), "r"(a[2]), "r"(a[3]), "r"(b0), "r"(b1));
}
__device__ __forceinline__ void split2(float a, float b, uint32_t& h, uint32_t& l) {
    __nv_bfloat162 hb = __floats2bfloat162_rn(a, b);
    __nv_bfloat162 lb = __floats2bfloat162_rn(a - __bfloat162float(hb.x),
                                              b - __bfloat162float(hb.y));
    h = *reinterpret_cast<uint32_t*>(&hb);
    l = *reinterpret_cast<uint32_t*>(&lb);
}

// ---------------- prep: feat -> padded hi/lo planes [flat][96] --------------
__global__ __launch_bounds__(128) void split_feat_kernel(const float* __restrict__ feat)
{
    int flat = blockIdx.x * 128 + threadIdx.x;
    if (flat >= NPX) return;
    int xp = flat % Wp, yp = (flat / Wp) % Hp, n = flat / (Hp * Wp);
    bool interior = (yp >= 1 && yp <= cH && xp >= 1 && xp <= cW);
    __nv_bfloat16* dh = g_A1h + (size_t)flat * CIN1;
    __nv_bfloat16* dl = g_A1l + (size_t)flat * CIN1;
    #pragma unroll
    for (int c = 0; c < 3; c++) {
        uint32_t hw[16], lw[16];
        if (interior) {
            const float* src = feat + ((size_t)(n * CIN1 + c * 32) * cH + (yp - 1)) * cW + (xp - 1);
            #pragma unroll
            for (int i = 0; i < 16; i++)
                split2(src[(size_t)(2 * i) * HW], src[(size_t)(2 * i + 1) * HW], hw[i], lw[i]);
        } else {
            #pragma unroll
            for (int i = 0; i < 16; i++) { hw[i] = 0; lw[i] = 0; }
        }
        #pragma unroll
        for (int j = 0; j < 4; j++) {
            *reinterpret_cast<uint4*>(dh + c * 32 + j * 8) = *reinterpret_cast<uint4*>(hw + j * 4);
            *reinterpret_cast<uint4*>(dl + c * 32 + j * 8) = *reinterpret_cast<uint4*>(lw + j * 4);
        }
    }
}

__global__ __launch_bounds__(128) void halo2_kernel()
{
    int flat = blockIdx.x * 128 + threadIdx.x;
    if (flat >= NPX) return;
    int xp = flat % Wp, yp = (flat / Wp) % Hp;
    if (yp >= 1 && yp <= cH && xp >= 1 && xp <= cW) return;
    uint4 z = {0, 0, 0, 0};
    uint4* dh = reinterpret_cast<uint4*>(g_A2h + (size_t)flat * CIN2);
    uint4* dl = reinterpret_cast<uint4*>(g_A2l + (size_t)flat * CIN2);
    #pragma unroll
    for (int j = 0; j < 16; j++) { dh[j] = z; dl[j] = z; }
}

// weights OIHW fp32 -> [pos][chunk][slab(h,l)][co][32] bf16
template<int CIN, int NCO>
__global__ __launch_bounds__(256) void split_w_kernel(const float* __restrict__ wt,
                                                      __nv_bfloat16* __restrict__ out)
{
    constexpr int NCH = CIN / 32;
    int idx = blockIdx.x * 256 + threadIdx.x;
    if (idx >= 9 * NCH * 2 * NCO * 32) return;
    int k = idx & 31; int t = idx >> 5;
    int co = t % NCO; t /= NCO;
    int slab = t % 2;  t /= 2;
    int chunk = t % NCH;
    int pos = t / NCH;
    float w = wt[((size_t)co * CIN + chunk * 32 + k) * 9 + pos];
    __nv_bfloat16 h = __float2bfloat16(w);
    out[idx] = (slab == 0) ? h : __float2bfloat16(w - __bfloat162float(h));
}

// ---------------- HMMA conv: CTA = 128px x NCO, 8 warps (4M x 2N) -----------
template<int CIN, int NCO, bool EPI1>
__global__ __launch_bounds__(256, 2) void conv_mma_kernel(
    const __nv_bfloat16* __restrict__ Ah, const __nv_bfloat16* __restrict__ Al,
    const __nv_bfloat16* __restrict__ Wv, const float* __restrict__ bias,
    float* __restrict__ maskOut)
{
    constexpr int NCH = CIN / 32;
    constexpr int R   = 9 * NCH;               // rounds (pos x chunk)
    constexpr int WN  = NCO / 2;                // co per warp-N group
    constexpr int NT  = NCO / 16;               // n-tiles per warp (8 / 9)
    constexpr int AB  = 128 * 80;               // one A plane buffer (padded rows)
    constexpr int SB  = 2 * AB + 2 * NCO * 80;  // full round buffer

    extern __shared__ __align__(16) char smem[];
    const uint32_t s0 = smem_u32(smem);

    const int tid = threadIdx.x, lane = tid & 31, wid = tid >> 5;
    const int warpM = wid & 3, warpN = wid >> 2;
    const int g = lane >> 2, t4 = (lane & 3) * 4;

    const int x0 = blockIdx.x * 128, y = blockIdx.y, n = blockIdx.z;

    float acc[2][NT][4];
    #pragma unroll
    for (int mi = 0; mi < 2; mi++)
        #pragma unroll
        for (int ni = 0; ni < NT; ni++)
            #pragma unroll
            for (int j = 0; j < 4; j++) acc[mi][ni][j] = 0.0f;

    auto issue = [&](int r, int buf) {
        const int pos = r / NCH, chunk = r - pos * NCH;
        const int ky = pos / 3, kx = pos - ky * 3;
        const size_t fb = ((size_t)(n * Hp) + y + ky) * Wp + x0 + kx;
        const uint32_t sb = s0 + buf * SB;
        // A: hi+lo planes, 128 rows x 32 k (64B) each -> 1024 x 16B
        #pragma unroll
        for (int i = 0; i < 4; i++) {
            int idx = i * 256 + tid;
            int pl = idx >> 9, rr = (idx >> 2) & 127, j = idx & 3;
            const __nv_bfloat16* src = (pl ? Al : Ah) + (fb + rr) * CIN + chunk * 32 + j * 8;
            cpa16(sb + pl * AB + rr * 80 + j * 16, src);
        }
        // B: Wh+Wl slabs, 2*NCO rows x 64B
        const __nv_bfloat16* ws = Wv + (size_t)(pos * NCH + chunk) * 2 * NCO * 32;
        for (int idx = tid; idx < 2 * NCO * 4; idx += 256) {
            int rr = idx >> 2, j = idx & 3;
            cpa16(sb + 2 * AB + rr * 80 + j * 16, ws + rr * 32 + j * 8);
        }
        asm volatile("cp.async.commit_group;" ::: "memory");
    };

    auto compute = [&](int buf) {
        const uint32_t sb = s0 + buf * SB;
        #pragma unroll
        for (int t = 0; t < 3; t++) {            // xh*wh, xl*wh, xh*wl
            const uint32_t Abase = sb + (t == 1 ? AB : 0);
            const uint32_t Bbase = sb + 2 * AB + (t == 2 ? NCO * 80 : 0);
            #pragma unroll
            for (int kh = 0; kh < 2; kh++) {
                const uint32_t ko = kh * 32;
                uint32_t a[2][4];
                #pragma unroll
                for (int mi = 0; mi < 2; mi++) {
                    uint32_t r0 = Abase + (warpM * 32 + mi * 16 + g) * 80 + ko + t4;
                    a[mi][0] = lds32(r0);        a[mi][1] = lds32(r0 + 640);
                    a[mi][2] = lds32(r0 + 16);   a[mi][3] = lds32(r0 + 656);
                }
                #pragma unroll
                for (int ni = 0; ni < NT; ni++) {
                    uint32_t rb = Bbase + (warpN * WN + ni * 8 + g) * 80 + ko + t4;
                    uint32_t b0 = lds32(rb), b1 = lds32(rb + 16);
                    mma_bf16(acc[0][ni], a[0], b0, b1);
                    mma_bf16(acc[1][ni], a[1], b0, b1);
                }
            }
        }
    };

    issue(0, 0);
    for (int r = 0; r < R; r++) {
        if (r + 1 < R) {
            issue(r + 1, (r + 1) & 1);
            asm volatile("cp.async.wait_group 1;" ::: "memory");
        } else {
            asm volatile("cp.async.wait_group 0;" ::: "memory");
        }
        __syncthreads();
        compute(r & 1);
        __syncthreads();
    }

    // ---------------- epilogue ----------------
    const int t2 = (lane & 3) * 2;
    #pragma unroll
    for (int mi = 0; mi < 2; mi++) {
        #pragma unroll
        for (int rr = 0; rr < 2; rr++) {
            const int px = x0 + warpM * 32 + mi * 16 + g + rr * 8;   // global x
            if (EPI1) {
                const size_t flat = ((size_t)(n * Hp) + y + 1) * Wp + px + 1;
                __nv_bfloat16* dh = g_A2h + flat * CIN2;
                __nv_bfloat16* dl = g_A2l + flat * CIN2;
                #pragma unroll
                for (int ni = 0; ni < NT; ni++) {
                    const int co = warpN * WN + ni * 8 + t2;
                    float v0 = acc[mi][ni][rr * 2 + 0] + __ldg(bias + co);
                    float v1 = acc[mi][ni][rr * 2 + 1] + __ldg(bias + co + 1);
                    v0 = v0 > 0.f ? v0 : 0.1f * v0;
                    v1 = v1 > 0.f ? v1 : 0.1f * v1;
                    uint32_t h, l;
                    split2(v0, v1, h, l);
                    *reinterpret_cast<uint32_t*>(dh + co) = h;
                    *reinterpret_cast<uint32_t*>(dl + co) = l;
                }
            } else {
                #pragma unroll
                for (int ni = 0; ni < NT; ni++) {
                    const int co = warpN * WN + ni * 8 + t2;
                    float v0 = acc[mi][ni][rr * 2 + 0] + __ldg(bias + co);
                    float v1 = acc[mi][ni][rr * 2 + 1] + __ldg(bias + co + 1);
                    size_t o = ((size_t)(n * COUT2 + co) * cH + y) * cW + px;
                    maskOut[o]      = v0;
                    maskOut[o + HW] = v1;
                }
            }
        }
    }
}

// ---------------- softmax + convex upsample + pixel shuffle -----------------
__global__ __launch_bounds__(256)
void upsample_kernel(const float* __restrict__ flow,
                     const float* __restrict__ mask, float* __restrict__ out)
{
    const int idx = blockIdx.x * blockDim.x + threadIdx.x;
    if (idx >= cN * HW) return;
    const int x = idx % cW, y = (idx / cW) % cH, n = idx / HW;

    float fpx[9], fpy[9];
    #pragma unroll
    for (int ki = 0; ki < 3; ki++)
        #pragma unroll
        for (int kj = 0; kj < 3; kj++) {
            const int k = ki * 3 + kj;
            const int yy = y + ki - 1, xx = x + kj - 1;
            const bool ok = (unsigned)yy < (unsigned)cH && (unsigned)xx < (unsigned)cW;
            fpx[k] = ok ? 4.0f * flow[(n * 2 + 0) * HW + yy * cW + xx] : 0.0f;
            fpy[k] = ok ? 4.0f * flow[(n * 2 + 1) * HW + yy * cW + xx] : 0.0f;
        }
    const size_t base = (size_t)n * COUT2 * HW + y * cW + x;
    const int OH = 4 * cH, OW = 4 * cW;
    #pragma unroll
    for (int a = 0; a < 4; a++)
        #pragma unroll
        for (int b = 0; b < 4; b++) {
            float m[9], mx = -1e30f;
            #pragma unroll
            for (int k = 0; k < 9; k++) {
                m[k] = 0.25f * mask[base + (size_t)(k * 16 + a * 4 + b) * HW];
                mx = fmaxf(mx, m[k]);
            }
            float s = 0.0f;
            #pragma unroll
            for (int k = 0; k < 9; k++) { m[k] = __expf(m[k] - mx); s += m[k]; }
            const float inv = 1.0f / s;
            float ox = 0.0f, oy = 0.0f;
            #pragma unroll
            for (int k = 0; k < 9; k++) { ox += m[k] * fpx[k]; oy += m[k] * fpy[k]; }
            const int oyi = y * 4 + a, oxi = x * 4 + b;
            out[((size_t)(n * 2 + 0) * OH + oyi) * OW + oxi] = ox * inv;
            out[((size_t)(n * 2 + 1) * OH + oyi) * OW + oxi] = oy * inv;
        }
}

// ---------------------------------------------------------------------------
extern "C" void kernel_launch(void* const* d_in, const int* in_sizes, int n_in,
                              void* d_out, int out_size)
{
    (void)in_sizes; (void)n_in; (void)out_size;
    const float* flow = (const float*)d_in[0];
    const float* feat = (const float*)d_in[1];
    const float* w1   = (const float*)d_in[2];
    const float* b1   = (const float*)d_in[3];
    const float* w2   = (const float*)d_in[4];
    const float* b2   = (const float*)d_in[5];
    float* out = (float*)d_out;

    __nv_bfloat16 *a1h, *a1l, *a2h, *a2l, *w1s, *w2s; float* msk;
    cudaGetSymbolAddress((void**)&a1h, g_A1h);
    cudaGetSymbolAddress((void**)&a1l, g_A1l);
    cudaGetSymbolAddress((void**)&a2h, g_A2h);
    cudaGetSymbolAddress((void**)&a2l, g_A2l);
    cudaGetSymbolAddress((void**)&w1s, g_W1);
    cudaGetSymbolAddress((void**)&w2s, g_W2);
    cudaGetSymbolAddress((void**)&msk, g_mask);

    constexpr int SM1 = 2 * (2 * 128 * 80 + 2 * COUT1 * 80);   // 81920
    constexpr int SM2 = 2 * (2 * 128 * 80 + 2 * COUT2 * 80);   // 87040
    cudaFuncSetAttribute(conv_mma_kernel<CIN1, COUT1, true>,
                         cudaFuncAttributeMaxDynamicSharedMemorySize, SM1);
    cudaFuncSetAttribute(conv_mma_kernel<CIN2, COUT2, false>,
                         cudaFuncAttributeMaxDynamicSharedMemorySize, SM2);

    split_feat_kernel<<<(NPX + 127) / 128, 128>>>(feat);
    halo2_kernel<<<(NPX + 127) / 128, 128>>>();
    split_w_kernel<CIN1, COUT1><<<(9 * 3 * 2 * COUT1 * 32 + 255) / 256, 256>>>(w1, w1s);
    split_w_kernel<CIN2, COUT2><<<(9 * 4 * 2 * COUT2 * 32 + 255) / 256, 256>>>(w2, w2s);

    conv_mma_kernel<CIN1, COUT1, true ><<<dim3(2, cH, cN), 256, SM1>>>(a1h, a1l, w1s, b1, msk);
    conv_mma_kernel<CIN2, COUT2, false><<<dim3(2, cH, cN), 256, SM2>>>(a2h, a2l, w2s, b2, msk);

    upsample_kernel<<<(cN * HW + 255) / 256, 256>>>(flow, msk, out);
}

// round 10
// speedup vs baseline: 2.7387x; 1.1092x over previous
#include <cuda_runtime.h>
#include <cuda_bf16.h>
#include <cstdint>
#include <math.h>

constexpr int cN = 4, cH = 128, cW = 256;
constexpr int CIN1 = 96,  COUT1 = 128;
constexpr int CIN2 = 128, COUT2 = 144;
constexpr int HW = cH * cW, Hp = cH + 2, Wp = cW + 2;
constexpr int NPX = cN * Hp * Wp;

// Static scratch (16B-aligned for cp.async / uint4)
__device__ __align__(256) __nv_bfloat16 g_A1h[(size_t)NPX * CIN1];
__device__ __align__(256) __nv_bfloat16 g_A1l[(size_t)NPX * CIN1];
__device__ __align__(256) __nv_bfloat16 g_A2h[(size_t)NPX * CIN2];
__device__ __align__(256) __nv_bfloat16 g_A2l[(size_t)NPX * CIN2];
__device__ __align__(256) __nv_bfloat16 g_W1[9 * 3 * 2 * COUT1 * 32];
__device__ __align__(256) __nv_bfloat16 g_W2[9 * 4 * 2 * COUT2 * 32];
__device__ __align__(256) float g_mask[(size_t)cN * COUT2 * HW];

// ---------------- helpers ----------------------------------------------------
__device__ __forceinline__ uint32_t smem_u32(const void* p) {
    uint32_t a;
    asm("{ .reg .u64 t; cvta.to.shared.u64 t, %1; cvt.u32.u64 %0, t; }" : "=r"(a) : "l"(p));
    return a;
}
__device__ __forceinline__ void cpa16(uint32_t s, const void* g) {
    asm volatile("cp.async.cg.shared.global [%0], [%1], 16;" :: "r"(s), "l"(g) : "memory");
}
__device__ __forceinline__ void ldsm_x4(uint32_t a, uint32_t* r) {
    asm volatile("ldmatrix.sync.aligned.m8n8.x4.shared.b16 {%0,%1,%2,%3}, [%4];"
                 : "=r"(r[0]), "=r"(r[1]), "=r"(r[2]), "=r"(r[3]) : "r"(a));
}
__device__ __forceinline__ void ldsm_x2(uint32_t a, uint32_t* r) {
    asm volatile("ldmatrix.sync.aligned.m8n8.x2.shared.b16 {%0,%1}, [%2];"
                 : "=r"(r[0]), "=r"(r[1]) : "r"(a));
}
__device__ __forceinline__ void mma_bf16(float* d, const uint32_t* a, uint32_t b0, uint32_t b1) {
    asm volatile("mma.sync.aligned.m16n8k16.row.col.f32.bf16.bf16.f32 "
        "{%0,%1,%2,%3}, {%4,%5,%6,%7}, {%8,%9}, {%0,%1,%2,%3};"
        : "+f"(d[0]), "+f"(d[1]), "+f"(d[2]), "+f"(d[3])
        : "r"(a[0]), "r"(a[1]), "r"(a[2]), "r"(a[3]), "r"(b0), "r"(b1));
}
__device__ __forceinline__ void split2(float a, float b, uint32_t& h, uint32_t& l) {
    __nv_bfloat162 hb = __floats2bfloat162_rn(a, b);
    __nv_bfloat162 lb = __floats2bfloat162_rn(a - __bfloat162float(hb.x),
                                              b - __bfloat162float(hb.y));
    h = *reinterpret_cast<uint32_t*>(&hb);
    l = *reinterpret_cast<uint32_t*>(&lb);
}

// ---------------- prep: feat -> padded hi/lo planes [flat][96] --------------
__global__ __launch_bounds__(128) void split_feat_kernel(const float* __restrict__ feat)
{
    int flat = blockIdx.x * 128 + threadIdx.x;
    if (flat >= NPX) return;
    int xp = flat % Wp, yp = (flat / Wp) % Hp, n = flat / (Hp * Wp);
    bool interior = (yp >= 1 && yp <= cH && xp >= 1 && xp <= cW);
    __nv_bfloat16* dh = g_A1h + (size_t)flat * CIN1;
    __nv_bfloat16* dl = g_A1l + (size_t)flat * CIN1;
    #pragma unroll
    for (int c = 0; c < 3; c++) {
        uint32_t hw[16], lw[16];
        if (interior) {
            const float* src = feat + ((size_t)(n * CIN1 + c * 32) * cH + (yp - 1)) * cW + (xp - 1);
            #pragma unroll
            for (int i = 0; i < 16; i++)
                split2(src[(size_t)(2 * i) * HW], src[(size_t)(2 * i + 1) * HW], hw[i], lw[i]);
        } else {
            #pragma unroll
            for (int i = 0; i < 16; i++) { hw[i] = 0; lw[i] = 0; }
        }
        #pragma unroll
        for (int j = 0; j < 4; j++) {
            *reinterpret_cast<uint4*>(dh + c * 32 + j * 8) = *reinterpret_cast<uint4*>(hw + j * 4);
            *reinterpret_cast<uint4*>(dl + c * 32 + j * 8) = *reinterpret_cast<uint4*>(lw + j * 4);
        }
    }
}

__global__ __launch_bounds__(128) void halo2_kernel()
{
    int flat = blockIdx.x * 128 + threadIdx.x;
    if (flat >= NPX) return;
    int xp = flat % Wp, yp = (flat / Wp) % Hp;
    if (yp >= 1 && yp <= cH && xp >= 1 && xp <= cW) return;
    uint4 z = {0, 0, 0, 0};
    uint4* dh = reinterpret_cast<uint4*>(g_A2h + (size_t)flat * CIN2);
    uint4* dl = reinterpret_cast<uint4*>(g_A2l + (size_t)flat * CIN2);
    #pragma unroll
    for (int j = 0; j < 16; j++) { dh[j] = z; dl[j] = z; }
}

// weights OIHW fp32 -> [pos][chunk][slab(h,l)][co][32] bf16
template<int CIN, int NCO>
__global__ __launch_bounds__(256) void split_w_kernel(const float* __restrict__ wt,
                                                      __nv_bfloat16* __restrict__ out)
{
    constexpr int NCH = CIN / 32;
    int idx = blockIdx.x * 256 + threadIdx.x;
    if (idx >= 9 * NCH * 2 * NCO * 32) return;
    int k = idx & 31; int t = idx >> 5;
    int co = t % NCO; t /= NCO;
    int slab = t % 2;  t /= 2;
    int chunk = t % NCH;
    int pos = t / NCH;
    float w = wt[((size_t)co * CIN + chunk * 32 + k) * 9 + pos];
    __nv_bfloat16 h = __float2bfloat16(w);
    out[idx] = (slab == 0) ? h : __float2bfloat16(w - __bfloat162float(h));
}

// ---------------- HMMA conv: CTA = 128px x NCO, 8 warps (4M x 2N) -----------
// Fragments loaded ONCE per k-half via ldmatrix; 3 split-term combos reuse them.
template<int CIN, int NCO, bool EPI1>
__global__ __launch_bounds__(256, 2) void conv_mma_kernel(
    const __nv_bfloat16* __restrict__ Ah, const __nv_bfloat16* __restrict__ Al,
    const __nv_bfloat16* __restrict__ Wv, const float* __restrict__ bias,
    float* __restrict__ maskOut)
{
    constexpr int NCH = CIN / 32;
    constexpr int R   = 9 * NCH;               // rounds (pos x chunk)
    constexpr int WN  = NCO / 2;                // co per warp-N group
    constexpr int NT  = NCO / 16;               // n-tiles per warp (8 / 9)
    constexpr int NPAIR = NT / 2;
    constexpr int AB  = 128 * 80;               // one A plane buffer (padded rows)
    constexpr int SB  = 2 * AB + 2 * NCO * 80;  // full round buffer

    extern __shared__ __align__(16) char smem[];
    const uint32_t s0 = smem_u32(smem);

    const int tid = threadIdx.x, lane = tid & 31, wid = tid >> 5;
    const int warpM = wid & 3, warpN = wid >> 2;
    const int g = lane >> 2;

    // ldmatrix per-lane address offsets (80B-padded rows; conflict-free)
    const uint32_t aoff = (uint32_t)((lane & 15) * 80 + (lane >> 4) * 16);
    const uint32_t boff = (uint32_t)((((lane >> 4) << 3) + (lane & 7)) * 80 + ((lane >> 3) & 1) * 16);
    const uint32_t boff2 = (uint32_t)((lane & 7) * 80 + ((lane >> 3) & 1) * 16);

    const int x0 = blockIdx.x * 128, y = blockIdx.y, n = blockIdx.z;

    float acc[2][NT][4];
    #pragma unroll
    for (int mi = 0; mi < 2; mi++)
        #pragma unroll
        for (int ni = 0; ni < NT; ni++)
            #pragma unroll
            for (int j = 0; j < 4; j++) acc[mi][ni][j] = 0.0f;

    auto issue = [&](int r, int buf) {
        const int pos = r / NCH, chunk = r - pos * NCH;
        const int ky = pos / 3, kx = pos - ky * 3;
        const size_t fb = ((size_t)(n * Hp) + y + ky) * Wp + x0 + kx;
        const uint32_t sb = s0 + buf * SB;
        #pragma unroll
        for (int i = 0; i < 4; i++) {
            int idx = i * 256 + tid;
            int pl = idx >> 9, rr = (idx >> 2) & 127, j = idx & 3;
            const __nv_bfloat16* src = (pl ? Al : Ah) + (fb + rr) * CIN + chunk * 32 + j * 8;
            cpa16(sb + pl * AB + rr * 80 + j * 16, src);
        }
        const __nv_bfloat16* ws = Wv + (size_t)(pos * NCH + chunk) * 2 * NCO * 32;
        for (int idx = tid; idx < 2 * NCO * 4; idx += 256) {
            int rr = idx >> 2, j = idx & 3;
            cpa16(sb + 2 * AB + rr * 80 + j * 16, ws + rr * 32 + j * 8);
        }
        asm volatile("cp.async.commit_group;" ::: "memory");
    };

    auto compute = [&](int buf) {
        const uint32_t sb  = s0 + buf * SB;
        const uint32_t Whb = sb + 2 * AB;
        const uint32_t Wlb = Whb + NCO * 80;
        #pragma unroll
        for (int kh = 0; kh < 2; kh++) {
            const uint32_t ko = kh * 32;
            uint32_t ah[2][4], al[2][4];
            #pragma unroll
            for (int mi = 0; mi < 2; mi++) {
                const uint32_t ab = (uint32_t)((warpM * 32 + mi * 16) * 80) + aoff + ko;
                ldsm_x4(sb + ab, ah[mi]);
                ldsm_x4(sb + AB + ab, al[mi]);
            }
            #pragma unroll
            for (int np = 0; np < NPAIR; np++) {
                const uint32_t nb = (uint32_t)((warpN * WN + np * 16) * 80) + boff + ko;
                uint32_t wh[4], wl[4];
                ldsm_x4(Whb + nb, wh);
                ldsm_x4(Wlb + nb, wl);
                #pragma unroll
                for (int mi = 0; mi < 2; mi++) {
                    mma_bf16(acc[mi][2 * np],     ah[mi], wh[0], wh[1]);
                    mma_bf16(acc[mi][2 * np + 1], ah[mi], wh[2], wh[3]);
                    mma_bf16(acc[mi][2 * np],     al[mi], wh[0], wh[1]);
                    mma_bf16(acc[mi][2 * np + 1], al[mi], wh[2], wh[3]);
                    mma_bf16(acc[mi][2 * np],     ah[mi], wl[0], wl[1]);
                    mma_bf16(acc[mi][2 * np + 1], ah[mi], wl[2], wl[3]);
                }
            }
            if (NT & 1) {   // odd tail tile (conv2: NT=9)
                const uint32_t nb = (uint32_t)((warpN * WN + (NT - 1) * 8) * 80) + boff2 + ko;
                uint32_t wh[2], wl[2];
                ldsm_x2(Whb + nb, wh);
                ldsm_x2(Wlb + nb, wl);
                #pragma unroll
                for (int mi = 0; mi < 2; mi++) {
                    mma_bf16(acc[mi][NT - 1], ah[mi], wh[0], wh[1]);
                    mma_bf16(acc[mi][NT - 1], al[mi], wh[0], wh[1]);
                    mma_bf16(acc[mi][NT - 1], ah[mi], wl[0], wl[1]);
                }
            }
        }
    };

    issue(0, 0);
    for (int r = 0; r < R; r++) {
        if (r + 1 < R) {
            issue(r + 1, (r + 1) & 1);
            asm volatile("cp.async.wait_group 1;" ::: "memory");
        } else {
            asm volatile("cp.async.wait_group 0;" ::: "memory");
        }
        __syncthreads();
        compute(r & 1);
        __syncthreads();
    }

    // ---------------- epilogue ----------------
    const int t2 = (lane & 3) * 2;
    #pragma unroll
    for (int mi = 0; mi < 2; mi++) {
        #pragma unroll
        for (int rr = 0; rr < 2; rr++) {
            const int px = x0 + warpM * 32 + mi * 16 + g + rr * 8;   // global x
            if (EPI1) {
                const size_t flat = ((size_t)(n * Hp) + y + 1) * Wp + px + 1;
                __nv_bfloat16* dh = g_A2h + flat * CIN2;
                __nv_bfloat16* dl = g_A2l + flat * CIN2;
                #pragma unroll
                for (int ni = 0; ni < NT; ni++) {
                    const int co = warpN * WN + ni * 8 + t2;
                    float v0 = acc[mi][ni][rr * 2 + 0] + __ldg(bias + co);
                    float v1 = acc[mi][ni][rr * 2 + 1] + __ldg(bias + co + 1);
                    v0 = v0 > 0.f ? v0 : 0.1f * v0;
                    v1 = v1 > 0.f ? v1 : 0.1f * v1;
                    uint32_t h, l;
                    split2(v0, v1, h, l);
                    *reinterpret_cast<uint32_t*>(dh + co) = h;
                    *reinterpret_cast<uint32_t*>(dl + co) = l;
                }
            } else {
                #pragma unroll
                for (int ni = 0; ni < NT; ni++) {
                    const int co = warpN * WN + ni * 8 + t2;
                    float v0 = acc[mi][ni][rr * 2 + 0] + __ldg(bias + co);
                    float v1 = acc[mi][ni][rr * 2 + 1] + __ldg(bias + co + 1);
                    size_t o = ((size_t)(n * COUT2 + co) * cH + y) * cW + px;
                    maskOut[o]      = v0;
                    maskOut[o + HW] = v1;
                }
            }
        }
    }
}

// ---------------- softmax + convex upsample + pixel shuffle -----------------
__global__ __launch_bounds__(256)
void upsample_kernel(const float* __restrict__ flow,
                     const float* __restrict__ mask, float* __restrict__ out)
{
    const int idx = blockIdx.x * blockDim.x + threadIdx.x;
    if (idx >= cN * HW) return;
    const int x = idx % cW, y = (idx / cW) % cH, n = idx / HW;

    float fpx[9], fpy[9];
    #pragma unroll
    for (int ki = 0; ki < 3; ki++)
        #pragma unroll
        for (int kj = 0; kj < 3; kj++) {
            const int k = ki * 3 + kj;
            const int yy = y + ki - 1, xx = x + kj - 1;
            const bool ok = (unsigned)yy < (unsigned)cH && (unsigned)xx < (unsigned)cW;
            fpx[k] = ok ? 4.0f * flow[(n * 2 + 0) * HW + yy * cW + xx] : 0.0f;
            fpy[k] = ok ? 4.0f * flow[(n * 2 + 1) * HW + yy * cW + xx] : 0.0f;
        }
    const size_t base = (size_t)n * COUT2 * HW + y * cW + x;
    const int OH = 4 * cH, OW = 4 * cW;
    #pragma unroll
    for (int a = 0; a < 4; a++)
        #pragma unroll
        for (int b = 0; b < 4; b++) {
            float m[9], mx = -1e30f;
            #pragma unroll
            for (int k = 0; k < 9; k++) {
                m[k] = 0.25f * mask[base + (size_t)(k * 16 + a * 4 + b) * HW];
                mx = fmaxf(mx, m[k]);
            }
            float s = 0.0f;
            #pragma unroll
            for (int k = 0; k < 9; k++) { m[k] = __expf(m[k] - mx); s += m[k]; }
            const float inv = 1.0f / s;
            float ox = 0.0f, oy = 0.0f;
            #pragma unroll
            for (int k = 0; k < 9; k++) { ox += m[k] * fpx[k]; oy += m[k] * fpy[k]; }
            const int oyi = y * 4 + a, oxi = x * 4 + b;
            out[((size_t)(n * 2 + 0) * OH + oyi) * OW + oxi] = ox * inv;
            out[((size_t)(n * 2 + 1) * OH + oyi) * OW + oxi] = oy * inv;
        }
}

// ---------------------------------------------------------------------------
extern "C" void kernel_launch(void* const* d_in, const int* in_sizes, int n_in,
                              void* d_out, int out_size)
{
    (void)in_sizes; (void)n_in; (void)out_size;
    const float* flow = (const float*)d_in[0];
    const float* feat = (const float*)d_in[1];
    const float* w1   = (const float*)d_in[2];
    const float* b1   = (const float*)d_in[3];
    const float* w2   = (const float*)d_in[4];
    const float* b2   = (const float*)d_in[5];
    float* out = (float*)d_out;

    __nv_bfloat16 *a1h, *a1l, *a2h, *a2l, *w1s, *w2s; float* msk;
    cudaGetSymbolAddress((void**)&a1h, g_A1h);
    cudaGetSymbolAddress((void**)&a1l, g_A1l);
    cudaGetSymbolAddress((void**)&a2h, g_A2h);
    cudaGetSymbolAddress((void**)&a2l, g_A2l);
    cudaGetSymbolAddress((void**)&w1s, g_W1);
    cudaGetSymbolAddress((void**)&w2s, g_W2);
    cudaGetSymbolAddress((void**)&msk, g_mask);

    constexpr int SM1 = 2 * (2 * 128 * 80 + 2 * COUT1 * 80);   // 81920
    constexpr int SM2 = 2 * (2 * 128 * 80 + 2 * COUT2 * 80);   // 87040
    cudaFuncSetAttribute(conv_mma_kernel<CIN1, COUT1, true>,
                         cudaFuncAttributeMaxDynamicSharedMemorySize, SM1);
    cudaFuncSetAttribute(conv_mma_kernel<CIN2, COUT2, false>,
                         cudaFuncAttributeMaxDynamicSharedMemorySize, SM2);

    split_feat_kernel<<<(NPX + 127) / 128, 128>>>(feat);
    halo2_kernel<<<(NPX + 127) / 128, 128>>>();
    split_w_kernel<CIN1, COUT1><<<(9 * 3 * 2 * COUT1 * 32 + 255) / 256, 256>>>(w1, w1s);
    split_w_kernel<CIN2, COUT2><<<(9 * 4 * 2 * COUT2 * 32 + 255) / 256, 256>>>(w2, w2s);

    conv_mma_kernel<CIN1, COUT1, true ><<<dim3(2, cH, cN), 256, SM1>>>(a1h, a1l, w1s, b1, msk);
    conv_mma_kernel<CIN2, COUT2, false><<<dim3(2, cH, cN), 256, SM2>>>(a2h, a2l, w2s, b2, msk);

    upsample_kernel<<<(cN * HW + 255) / 256, 256>>>(flow, msk, out);
}